// round 15
// baseline (speedup 1.0000x reference)
#include <cuda_runtime.h>

// PRNN_1769526526374: J2 plane-strain plasticity RNN.
// R15 = R14 with the polish exp made EXACT (R14's 3rd-order Taylor of
// exp(-dt) goes NEGATIVE for dt>~1.6, which large first-yield Halley
// overshoots do reach -> corrupted slope -> rel_err 3.8).
// Per half: cached-ivd seed (no MUFU) -> guarded Halley (exp+div) ->
// exact-exp Newton polish (exp+div; the div reciprocal i1 is reused as the
// next step's cached seed slope; bex refresh = 1st-order multiply on a
// now-tiny correction). 5 MUFU/half, Halley+Newton accuracy (~1e-5 band).
// Folded elastic-constant weights retained from R14 (-5 packed ops/pair).

namespace {
constexpr int Bb   = 4096;
constexpr int Ss   = 512;
constexpr int TPB  = 128;
constexpr int T    = 2;     // steps per reduction chunk
constexpr int ROWF = 388;   // F2 per part row (padded for reduce banks)

typedef unsigned long long F2;

__device__ __forceinline__ F2 pk2(float lo, float hi) {
    F2 r; asm("mov.b64 %0, {%1, %2};" : "=l"(r) : "f"(lo), "f"(hi)); return r;
}
__device__ __forceinline__ void upk2(F2 v, float& lo, float& hi) {
    asm("mov.b64 {%0, %1}, %2;" : "=f"(lo), "=f"(hi) : "l"(v));
}
__device__ __forceinline__ F2 mul2(F2 a, F2 b) {
    F2 r; asm("mul.rn.f32x2 %0, %1, %2;" : "=l"(r) : "l"(a), "l"(b)); return r;
}
__device__ __forceinline__ F2 add2(F2 a, F2 b) {
    F2 r; asm("add.rn.f32x2 %0, %1, %2;" : "=l"(r) : "l"(a), "l"(b)); return r;
}
__device__ __forceinline__ F2 fma2(F2 a, F2 b, F2 c) {
    F2 r; asm("fma.rn.f32x2 %0, %1, %2, %3;" : "=l"(r) : "l"(a), "l"(b), "l"(c)); return r;
}
} // namespace

__global__ void __launch_bounds__(TPB, 5) prnn_kernel(
    const float* __restrict__ x,    // [B,S,3]
    const float* __restrict__ W1,   // [384,3]
    const float* __restrict__ W2,   // [3,384]
    float* __restrict__ out)        // [B,S,3]
{
    const float MUv      = (float)(3130.0 / (2.0 * 1.3));
    const float TWO_MU   = 2.0f * MUv;
    const float THREE_MU = 3.0f * MUv;
    const float NEG3MU   = -THREE_MU;
    const float INV3MU   = 1.0f / THREE_MU;
    const float LAM      = (float)(3130.0 * 0.3 / (1.3 * 0.4));
    const float Kb       = LAM + (2.0f / 3.0f) * MUv;
    const float Ah = 64.8f, Bh = 33.6f;
    const float INV_C  = (float)(1.0 / 0.003407);
    const float NINV_C = -INV_C;
    const float INVC2  = INV_C * INV_C;      // 1/C^2

    const F2 C3 = pk2(3.0f, 3.0f);

    __shared__ F2 sx0[Ss * 3];          // 12.3 KB
    __shared__ F2 sx1[Ss * 3];          // 12.3 KB
    __shared__ F2 part[2 * T * ROWF];   // 12.4 KB

    const int tid = threadIdx.x;
    const int t3  = 3 * tid;
    const int b0  = 4 * blockIdx.x;

    const float* xb = x + (long)b0 * (Ss * 3);
    for (int i = tid; i < Ss * 3; i += TPB) {
        sx0[i] = pk2(xb[i],              xb[i + Ss * 3]);
        sx1[i] = pk2(xb[i + 2 * Ss * 3], xb[i + 3 * Ss * 3]);
    }

    // Fold elastic constants into per-point weights:
    //   s0_trial = dot(ws0, x) + ts0 ; s1_trial = dot(ws1, x) + ts1
    //   s3_trial = dot(ws3, x) + ts3 ; pressure = dot(wp, x)
    F2 ws0[3], ws1[3], ws3[3], wp[3], w2p[9];
    {
        const float r0x = W1[tid * 9 + 0], r0y = W1[tid * 9 + 1], r0z = W1[tid * 9 + 2];
        const float r1x = W1[tid * 9 + 3], r1y = W1[tid * 9 + 4], r1z = W1[tid * 9 + 5];
        const float r2x = W1[tid * 9 + 6], r2y = W1[tid * 9 + 7], r2z = W1[tid * 9 + 8];
        const float c23 = TWO_MU * (2.0f / 3.0f);
        const float c13 = TWO_MU * (1.0f / 3.0f);
        const float a0[3] = {c23 * r0x - c13 * r1x, c23 * r0y - c13 * r1y, c23 * r0z - c13 * r1z};
        const float a1[3] = {c23 * r1x - c13 * r0x, c23 * r1y - c13 * r0y, c23 * r1z - c13 * r0z};
        const float a3[3] = {MUv * r2x, MUv * r2y, MUv * r2z};
        const float ap[3] = {Kb * (r0x + r1x), Kb * (r0y + r1y), Kb * (r0z + r1z)};
#pragma unroll
        for (int j = 0; j < 3; ++j) {
            ws0[j] = pk2(a0[j], a0[j]);
            ws1[j] = pk2(a1[j], a1[j]);
            ws3[j] = pk2(a3[j], a3[j]);
            wp[j]  = pk2(ap[j], ap[j]);
        }
    }
#pragma unroll
    for (int o = 0; o < 3; ++o)
#pragma unroll
        for (int j = 0; j < 3; ++j) {
            float w = W2[o * 384 + t3 + j];
            w2p[o * 3 + j] = pk2(w, w);
        }

    // State per half: bex = B*exp(-kappa/C); ivd = 1/(3mu + bex/C).
    // Packed: ts_i = -2mu*ep_i for i in {xx,yy,xy} (zz via tracelessness).
    F2 ts[2][3];
#pragma unroll
    for (int p = 0; p < 2; ++p)
#pragma unroll
        for (int i = 0; i < 3; ++i) ts[p][i] = 0;
    float bex[4], ivd[4];
    const float ivd0 = 1.0f / (THREE_MU + Bh * INV_C);
#pragma unroll
    for (int h = 0; h < 4; ++h) { bex[h] = Bh; ivd[h] = ivd0; }

    float* ob = out + (long)b0 * (Ss * 3);

    __syncthreads();

    for (int s0i = 0; s0i < Ss; s0i += T) {
#pragma unroll
        for (int si = 0; si < T; ++si) {
            const int s = s0i + si;
#pragma unroll
            for (int p = 0; p < 2; ++p) {
                const F2* sxp = p ? sx1 : sx0;
                const F2 x0 = sxp[3 * s + 0];
                const F2 x1 = sxp[3 * s + 1];
                const F2 x2 = sxp[3 * s + 2];

                // trial deviatoric stress + pressure: folded dot products
                F2 s0d = fma2(ws0[0], x0, fma2(ws0[1], x1, fma2(ws0[2], x2, ts[p][0])));
                F2 s1d = fma2(ws1[0], x0, fma2(ws1[1], x1, fma2(ws1[2], x2, ts[p][1])));
                F2 s3d = fma2(ws3[0], x0, fma2(ws3[1], x1, fma2(ws3[2], x2, ts[p][2])));
                const F2 pr2 = fma2(wp[0], x0, fma2(wp[1], x1, mul2(wp[2], x2)));

                // qsq = 3*(s0^2 + s0*s1 + s1^2 + s3^2)
                F2 acc = mul2(s3d, s3d);
                acc = fma2(s1d, s1d, acc);
                acc = fma2(s0d, s1d, acc);
                acc = fma2(s0d, s0d, acc);
                const F2 qsq2 = mul2(C3, acc);

                float qsA, qsB;
                upk2(qsq2, qsA, qsB);
                qsA = fmaxf(qsA, 1e-24f);
                qsB = fmaxf(qsB, 1e-24f);
                const float rqA = rsqrtf(qsA);
                const float rqB = rsqrtf(qsB);
                const float qaA = qsA * rqA - Ah;   // q - A
                const float qaB = qsB * rqB - Ah;

                const float bxA = bex[2 * p], bxB = bex[2 * p + 1];

                // Seed: exact first Newton step from 0, cached slope (no MUFU)
                const float dg0A = fmaxf(qaA + bxA, 0.f) * ivd[2 * p];
                const float dg0B = fmaxf(qaB + bxB, 0.f) * ivd[2 * p + 1];

                // Guarded Halley iteration (cubic) at dg0.
                const float BekA = bxA * __expf(dg0A * NINV_C);
                const float BekB = bxB * __expf(dg0B * NINV_C);
                const float dA = fmaf(BekA, INV_C, THREE_MU);
                const float dB = fmaf(BekB, INV_C, THREE_MU);
                const float rA = fmaf(NEG3MU, dg0A, qaA) + BekA;
                const float rB = fmaf(NEG3MU, dg0B, qaB) + BekB;
                float denA = fmaf(-rA * BekA, INVC2, 2.f * dA * dA);
                float denB = fmaf(-rB * BekB, INVC2, 2.f * dB * dB);
                denA = fmaxf(denA, dA * dA);   // step <= 2x Newton
                denB = fmaxf(denB, dB * dB);
                float dgA = dg0A + __fdividef(2.f * rA * dA, denA);
                float dgB = dg0B + __fdividef(2.f * rB * dB, denB);
                dgA = fminf(dgA, fmaf(rA, INV3MU, dg0A));  // root upper bound
                dgB = fminf(dgB, fmaf(rB, INV3MU, dg0B));
                dgA = fmaxf(dgA, 0.f);
                dgB = fmaxf(dgB, 0.f);

                // Newton polish with EXACT exp (safe for any dt, unlike the
                // R14 Taylor). The divide's reciprocal i1 doubles as the next
                // step's cached seed slope.
                const float Bk1A = bxA * __expf(dgA * NINV_C);
                const float Bk1B = bxB * __expf(dgB * NINV_C);
                const float r1A = fmaf(NEG3MU, dgA, qaA) + Bk1A;
                const float r1B = fmaf(NEG3MU, dgB, qaB) + Bk1B;
                const float i1A = __fdividef(1.f, fmaf(Bk1A, INV_C, THREE_MU));
                const float i1B = __fdividef(1.f, fmaf(Bk1B, INV_C, THREE_MU));
                const float dg2A = fmaxf(fmaf(r1A, i1A, dgA), 0.f);
                const float dg2B = fmaxf(fmaf(r1B, i1B, dgB), 0.f);

                // state refresh: bex at final dg via 1st-order from Bk1
                // (|dg - dg2| is now ~1e-4*C at worst: correction << 1).
                bex[2 * p]     = Bk1A * fmaf(dgA - dg2A, INV_C, 1.f);
                bex[2 * p + 1] = Bk1B * fmaf(dgB - dg2B, INV_C, 1.f);
                ivd[2 * p]     = i1A;
                ivd[2 * p + 1] = i1B;

                // radial return: one packed coefficient for stress AND state
                const F2 NN2 = pk2(NEG3MU * dg2A * rqA, NEG3MU * dg2B * rqB);
                ts[p][0] = fma2(NN2, s0d, ts[p][0]);
                ts[p][1] = fma2(NN2, s1d, ts[p][1]);
                ts[p][2] = fma2(NN2, s3d, ts[p][2]);
                s0d = fma2(NN2, s0d, s0d);
                s1d = fma2(NN2, s1d, s1d);
                s3d = fma2(NN2, s3d, s3d);

                const F2 sig0 = add2(s0d, pr2);
                const F2 sig1 = add2(s1d, pr2);

                F2* prp = part + (p * T + si) * ROWF + t3;
                prp[0] = fma2(w2p[0], sig0, fma2(w2p[1], sig1, mul2(w2p[2], s3d)));
                prp[1] = fma2(w2p[3], sig0, fma2(w2p[4], sig1, mul2(w2p[5], s3d)));
                prp[2] = fma2(w2p[6], sig0, fma2(w2p[7], sig1, mul2(w2p[8], s3d)));
            }
        }
        __syncthreads();

        // Reduction: 12 items (pair, si, o) x 8 lanes = 96 threads (3 FULL
        // warps, every slot valid). Each lane sums 16 F2 (stride 8 points),
        // then 3-stage shfl within the 8-lane group; lane0 writes 2 floats.
        if (tid < 96) {
            const int item = tid >> 3;        // 0..11
            const int l8   = tid & 7;
            const int pair = item / (T * 3);
            const int rem  = item - (T * 3) * pair;
            const int si   = rem / 3;
            const int o    = rem - 3 * si;
            const F2* prp = part + (pair * T + si) * ROWF + o + 3 * l8;
            F2 a0 = 0, a1 = 0, a2 = 0, a3 = 0;
#pragma unroll
            for (int j = 0; j < 16; j += 4) {
                a0 = add2(a0, prp[24 * j]);
                a1 = add2(a1, prp[24 * (j + 1)]);
                a2 = add2(a2, prp[24 * (j + 2)]);
                a3 = add2(a3, prp[24 * (j + 3)]);
            }
            const F2 t = add2(add2(a0, a1), add2(a2, a3));
            float lo, hi;
            upk2(t, lo, hi);
            lo += __shfl_xor_sync(0xffffffffu, lo, 1);
            hi += __shfl_xor_sync(0xffffffffu, hi, 1);
            lo += __shfl_xor_sync(0xffffffffu, lo, 2);
            hi += __shfl_xor_sync(0xffffffffu, hi, 2);
            lo += __shfl_xor_sync(0xffffffffu, lo, 4);
            hi += __shfl_xor_sync(0xffffffffu, hi, 4);
            if ((tid & 7) == 0) {
                const int idx = (s0i + si) * 3 + o;
                ob[(long)(2 * pair) * (Ss * 3) + idx]     = lo;
                ob[(long)(2 * pair + 1) * (Ss * 3) + idx] = hi;
            }
        }
        __syncthreads();
    }
}

extern "C" void kernel_launch(void* const* d_in, const int* in_sizes, int n_in,
                              void* d_out, int out_size) {
    const float* x  = (const float*)d_in[0];
    const float* W1 = (const float*)d_in[1];
    const float* W2 = (const float*)d_in[2];
    prnn_kernel<<<Bb / 4, TPB>>>(x, W1, W2, (float*)d_out);
}

// round 16
// speedup vs baseline: 1.0756x; 1.0756x over previous
#include <cuda_runtime.h>

// PRNN_1769526526374: J2 plane-strain plasticity RNN.
// R16 = consolidation: R15 skeleton (folded elastic weights, T=2, 5 blk/SM)
// with the return mapping reduced to the dominant scheme found across
// R11/R13/R15:
//   seed dg0 = max(f,0)*ivd (cached reciprocal slope, no MUFU)
//   2 exact Newton iterations (exp+div each; iter2's reciprocal i2 is
//   reused as next step's ivd -> no extra divide)
//   bex refresh: 1st-order multiply on Bek2 (|dg1-dg2| tiny after 2 exact
//   iterations -- the safe regime, per R11)
// 5 MUFU/half like R13, but ~7 fewer scalar fma than the Halley variants,
// with R11-proven convergence (expected rel_err ~1.5e-5).

namespace {
constexpr int Bb   = 4096;
constexpr int Ss   = 512;
constexpr int TPB  = 128;
constexpr int T    = 2;     // steps per reduction chunk
constexpr int ROWF = 388;   // F2 per part row (padded for reduce banks)

typedef unsigned long long F2;

__device__ __forceinline__ F2 pk2(float lo, float hi) {
    F2 r; asm("mov.b64 %0, {%1, %2};" : "=l"(r) : "f"(lo), "f"(hi)); return r;
}
__device__ __forceinline__ void upk2(F2 v, float& lo, float& hi) {
    asm("mov.b64 {%0, %1}, %2;" : "=f"(lo), "=f"(hi) : "l"(v));
}
__device__ __forceinline__ F2 mul2(F2 a, F2 b) {
    F2 r; asm("mul.rn.f32x2 %0, %1, %2;" : "=l"(r) : "l"(a), "l"(b)); return r;
}
__device__ __forceinline__ F2 add2(F2 a, F2 b) {
    F2 r; asm("add.rn.f32x2 %0, %1, %2;" : "=l"(r) : "l"(a), "l"(b)); return r;
}
__device__ __forceinline__ F2 fma2(F2 a, F2 b, F2 c) {
    F2 r; asm("fma.rn.f32x2 %0, %1, %2, %3;" : "=l"(r) : "l"(a), "l"(b), "l"(c)); return r;
}
} // namespace

__global__ void __launch_bounds__(TPB, 5) prnn_kernel(
    const float* __restrict__ x,    // [B,S,3]
    const float* __restrict__ W1,   // [384,3]
    const float* __restrict__ W2,   // [3,384]
    float* __restrict__ out)        // [B,S,3]
{
    const float MUv      = (float)(3130.0 / (2.0 * 1.3));
    const float TWO_MU   = 2.0f * MUv;
    const float THREE_MU = 3.0f * MUv;
    const float NEG3MU   = -THREE_MU;
    const float LAM      = (float)(3130.0 * 0.3 / (1.3 * 0.4));
    const float Kb       = LAM + (2.0f / 3.0f) * MUv;
    const float Ah = 64.8f, Bh = 33.6f;
    const float INV_C  = (float)(1.0 / 0.003407);
    const float NINV_C = -INV_C;

    const F2 C3 = pk2(3.0f, 3.0f);

    __shared__ F2 sx0[Ss * 3];          // 12.3 KB
    __shared__ F2 sx1[Ss * 3];          // 12.3 KB
    __shared__ F2 part[2 * T * ROWF];   // 12.4 KB

    const int tid = threadIdx.x;
    const int t3  = 3 * tid;
    const int b0  = 4 * blockIdx.x;

    const float* xb = x + (long)b0 * (Ss * 3);
    for (int i = tid; i < Ss * 3; i += TPB) {
        sx0[i] = pk2(xb[i],              xb[i + Ss * 3]);
        sx1[i] = pk2(xb[i + 2 * Ss * 3], xb[i + 3 * Ss * 3]);
    }

    // Fold elastic constants into per-point weights:
    //   s0_trial = dot(ws0, x) + ts0 ; s1_trial = dot(ws1, x) + ts1
    //   s3_trial = dot(ws3, x) + ts3 ; pressure = dot(wp, x)
    F2 ws0[3], ws1[3], ws3[3], wp[3], w2p[9];
    {
        const float r0x = W1[tid * 9 + 0], r0y = W1[tid * 9 + 1], r0z = W1[tid * 9 + 2];
        const float r1x = W1[tid * 9 + 3], r1y = W1[tid * 9 + 4], r1z = W1[tid * 9 + 5];
        const float r2x = W1[tid * 9 + 6], r2y = W1[tid * 9 + 7], r2z = W1[tid * 9 + 8];
        const float c23 = TWO_MU * (2.0f / 3.0f);
        const float c13 = TWO_MU * (1.0f / 3.0f);
        const float a0[3] = {c23 * r0x - c13 * r1x, c23 * r0y - c13 * r1y, c23 * r0z - c13 * r1z};
        const float a1[3] = {c23 * r1x - c13 * r0x, c23 * r1y - c13 * r0y, c23 * r1z - c13 * r0z};
        const float a3[3] = {MUv * r2x, MUv * r2y, MUv * r2z};
        const float ap[3] = {Kb * (r0x + r1x), Kb * (r0y + r1y), Kb * (r0z + r1z)};
#pragma unroll
        for (int j = 0; j < 3; ++j) {
            ws0[j] = pk2(a0[j], a0[j]);
            ws1[j] = pk2(a1[j], a1[j]);
            ws3[j] = pk2(a3[j], a3[j]);
            wp[j]  = pk2(ap[j], ap[j]);
        }
    }
#pragma unroll
    for (int o = 0; o < 3; ++o)
#pragma unroll
        for (int j = 0; j < 3; ++j) {
            float w = W2[o * 384 + t3 + j];
            w2p[o * 3 + j] = pk2(w, w);
        }

    // State per half: bex = B*exp(-kappa/C); ivd = 1/(3mu + bex/C).
    // Packed: ts_i = -2mu*ep_i for i in {xx,yy,xy} (zz via tracelessness).
    F2 ts[2][3];
#pragma unroll
    for (int p = 0; p < 2; ++p)
#pragma unroll
        for (int i = 0; i < 3; ++i) ts[p][i] = 0;
    float bex[4], ivd[4];
    const float ivd0 = 1.0f / (THREE_MU + Bh * INV_C);
#pragma unroll
    for (int h = 0; h < 4; ++h) { bex[h] = Bh; ivd[h] = ivd0; }

    float* ob = out + (long)b0 * (Ss * 3);

    __syncthreads();

    for (int s0i = 0; s0i < Ss; s0i += T) {
#pragma unroll
        for (int si = 0; si < T; ++si) {
            const int s = s0i + si;
#pragma unroll
            for (int p = 0; p < 2; ++p) {
                const F2* sxp = p ? sx1 : sx0;
                const F2 x0 = sxp[3 * s + 0];
                const F2 x1 = sxp[3 * s + 1];
                const F2 x2 = sxp[3 * s + 2];

                // trial deviatoric stress + pressure: folded dot products
                F2 s0d = fma2(ws0[0], x0, fma2(ws0[1], x1, fma2(ws0[2], x2, ts[p][0])));
                F2 s1d = fma2(ws1[0], x0, fma2(ws1[1], x1, fma2(ws1[2], x2, ts[p][1])));
                F2 s3d = fma2(ws3[0], x0, fma2(ws3[1], x1, fma2(ws3[2], x2, ts[p][2])));
                const F2 pr2 = fma2(wp[0], x0, fma2(wp[1], x1, mul2(wp[2], x2)));

                // qsq = 3*(s0^2 + s0*s1 + s1^2 + s3^2)
                F2 acc = mul2(s3d, s3d);
                acc = fma2(s1d, s1d, acc);
                acc = fma2(s0d, s1d, acc);
                acc = fma2(s0d, s0d, acc);
                const F2 qsq2 = mul2(C3, acc);

                float qsA, qsB;
                upk2(qsq2, qsA, qsB);
                qsA = fmaxf(qsA, 1e-24f);
                qsB = fmaxf(qsB, 1e-24f);
                const float rqA = rsqrtf(qsA);
                const float rqB = rsqrtf(qsB);
                const float qaA = qsA * rqA - Ah;   // q - A
                const float qaB = qsB * rqB - Ah;

                const float bxA = bex[2 * p], bxB = bex[2 * p + 1];

                // Seed: exact first Newton step from 0, cached slope (no MUFU)
                const float dg0A = fmaxf(qaA + bxA, 0.f) * ivd[2 * p];
                const float dg0B = fmaxf(qaB + bxB, 0.f) * ivd[2 * p + 1];

                // Newton iteration 1 (exact exp)
                const float BekA = bxA * __expf(dg0A * NINV_C);
                const float BekB = bxB * __expf(dg0B * NINV_C);
                const float rA = fmaf(NEG3MU, dg0A, qaA) + BekA;
                const float rB = fmaf(NEG3MU, dg0B, qaB) + BekB;
                const float dg1A = fmaxf(dg0A + __fdividef(rA, fmaf(BekA, INV_C, THREE_MU)), 0.f);
                const float dg1B = fmaxf(dg0B + __fdividef(rB, fmaf(BekB, INV_C, THREE_MU)), 0.f);

                // Newton iteration 2 (exact exp); reciprocal i2 doubles as
                // the next step's cached seed slope.
                const float Bk2A = bxA * __expf(dg1A * NINV_C);
                const float Bk2B = bxB * __expf(dg1B * NINV_C);
                const float r2A = fmaf(NEG3MU, dg1A, qaA) + Bk2A;
                const float r2B = fmaf(NEG3MU, dg1B, qaB) + Bk2B;
                const float i2A = __fdividef(1.f, fmaf(Bk2A, INV_C, THREE_MU));
                const float i2B = __fdividef(1.f, fmaf(Bk2B, INV_C, THREE_MU));
                const float dg2A = fmaxf(fmaf(r2A, i2A, dg1A), 0.f);
                const float dg2B = fmaxf(fmaf(r2B, i2B, dg1B), 0.f);

                // state refresh: bex at final dg via 1st-order from Bk2
                // (|dg1 - dg2| tiny after two exact iterations).
                bex[2 * p]     = Bk2A * fmaf(dg1A - dg2A, INV_C, 1.f);
                bex[2 * p + 1] = Bk2B * fmaf(dg1B - dg2B, INV_C, 1.f);
                ivd[2 * p]     = i2A;
                ivd[2 * p + 1] = i2B;

                // radial return: one packed coefficient for stress AND state
                const F2 NN2 = pk2(NEG3MU * dg2A * rqA, NEG3MU * dg2B * rqB);
                ts[p][0] = fma2(NN2, s0d, ts[p][0]);
                ts[p][1] = fma2(NN2, s1d, ts[p][1]);
                ts[p][2] = fma2(NN2, s3d, ts[p][2]);
                s0d = fma2(NN2, s0d, s0d);
                s1d = fma2(NN2, s1d, s1d);
                s3d = fma2(NN2, s3d, s3d);

                const F2 sig0 = add2(s0d, pr2);
                const F2 sig1 = add2(s1d, pr2);

                F2* prp = part + (p * T + si) * ROWF + t3;
                prp[0] = fma2(w2p[0], sig0, fma2(w2p[1], sig1, mul2(w2p[2], s3d)));
                prp[1] = fma2(w2p[3], sig0, fma2(w2p[4], sig1, mul2(w2p[5], s3d)));
                prp[2] = fma2(w2p[6], sig0, fma2(w2p[7], sig1, mul2(w2p[8], s3d)));
            }
        }
        __syncthreads();

        // Reduction: 12 items (pair, si, o) x 8 lanes = 96 threads (3 FULL
        // warps, every slot valid). Each lane sums 16 F2 (stride 8 points),
        // then 3-stage shfl within the 8-lane group; lane0 writes 2 floats.
        if (tid < 96) {
            const int item = tid >> 3;        // 0..11
            const int l8   = tid & 7;
            const int pair = item / (T * 3);
            const int rem  = item - (T * 3) * pair;
            const int si   = rem / 3;
            const int o    = rem - 3 * si;
            const F2* prp = part + (pair * T + si) * ROWF + o + 3 * l8;
            F2 a0 = 0, a1 = 0, a2 = 0, a3 = 0;
#pragma unroll
            for (int j = 0; j < 16; j += 4) {
                a0 = add2(a0, prp[24 * j]);
                a1 = add2(a1, prp[24 * (j + 1)]);
                a2 = add2(a2, prp[24 * (j + 2)]);
                a3 = add2(a3, prp[24 * (j + 3)]);
            }
            const F2 t = add2(add2(a0, a1), add2(a2, a3));
            float lo, hi;
            upk2(t, lo, hi);
            lo += __shfl_xor_sync(0xffffffffu, lo, 1);
            hi += __shfl_xor_sync(0xffffffffu, hi, 1);
            lo += __shfl_xor_sync(0xffffffffu, lo, 2);
            hi += __shfl_xor_sync(0xffffffffu, hi, 2);
            lo += __shfl_xor_sync(0xffffffffu, lo, 4);
            hi += __shfl_xor_sync(0xffffffffu, hi, 4);
            if ((tid & 7) == 0) {
                const int idx = (s0i + si) * 3 + o;
                ob[(long)(2 * pair) * (Ss * 3) + idx]     = lo;
                ob[(long)(2 * pair + 1) * (Ss * 3) + idx] = hi;
            }
        }
        __syncthreads();
    }
}

extern "C" void kernel_launch(void* const* d_in, const int* in_sizes, int n_in,
                              void* d_out, int out_size) {
    const float* x  = (const float*)d_in[0];
    const float* W1 = (const float*)d_in[1];
    const float* W2 = (const float*)d_in[2];
    prnn_kernel<<<Bb / 4, TPB>>>(x, W1, W2, (float*)d_out);
}

// round 17
// speedup vs baseline: 1.0919x; 1.0151x over previous
#include <cuda_runtime.h>

// PRNN_1769526526374: J2 plane-strain plasticity RNN.
// R17 = R16 mainloop (folded weights, cached-seed + 2 exact Newton), with
// launch geometry fixed for wave quantization: 1 packed pair (2 batches)
// per thread, grid 2048, __launch_bounds__(128,7).
//   capacity 148x7 = 1036 -> waves 1036 + 1012 (98% full) ~ 99% utilization
//   AND 28 resident warps/SM (vs 20). R16's grid-1024/5-block config wasted
//   ~25% in a 38%-full second wave (measured occ 24.8% vs 31.25% resident).
// Reduction: 6 items (si,o) x 16 lanes = 96 threads (3 FULL warps, all
// valid), 8 F2 per lane + 4-stage shfl.

namespace {
constexpr int Bb   = 4096;
constexpr int Ss   = 512;
constexpr int TPB  = 128;
constexpr int T    = 2;     // steps per reduction chunk
constexpr int ROWF = 388;   // F2 per part row (padded for reduce banks)

typedef unsigned long long F2;

__device__ __forceinline__ F2 pk2(float lo, float hi) {
    F2 r; asm("mov.b64 %0, {%1, %2};" : "=l"(r) : "f"(lo), "f"(hi)); return r;
}
__device__ __forceinline__ void upk2(F2 v, float& lo, float& hi) {
    asm("mov.b64 {%0, %1}, %2;" : "=f"(lo), "=f"(hi) : "l"(v));
}
__device__ __forceinline__ F2 mul2(F2 a, F2 b) {
    F2 r; asm("mul.rn.f32x2 %0, %1, %2;" : "=l"(r) : "l"(a), "l"(b)); return r;
}
__device__ __forceinline__ F2 add2(F2 a, F2 b) {
    F2 r; asm("add.rn.f32x2 %0, %1, %2;" : "=l"(r) : "l"(a), "l"(b)); return r;
}
__device__ __forceinline__ F2 fma2(F2 a, F2 b, F2 c) {
    F2 r; asm("fma.rn.f32x2 %0, %1, %2, %3;" : "=l"(r) : "l"(a), "l"(b), "l"(c)); return r;
}
} // namespace

__global__ void __launch_bounds__(TPB, 7) prnn_kernel(
    const float* __restrict__ x,    // [B,S,3]
    const float* __restrict__ W1,   // [384,3]
    const float* __restrict__ W2,   // [3,384]
    float* __restrict__ out)        // [B,S,3]
{
    const float MUv      = (float)(3130.0 / (2.0 * 1.3));
    const float TWO_MU   = 2.0f * MUv;
    const float THREE_MU = 3.0f * MUv;
    const float NEG3MU   = -THREE_MU;
    const float LAM      = (float)(3130.0 * 0.3 / (1.3 * 0.4));
    const float Kb       = LAM + (2.0f / 3.0f) * MUv;
    const float Ah = 64.8f, Bh = 33.6f;
    const float INV_C  = (float)(1.0 / 0.003407);
    const float NINV_C = -INV_C;

    const F2 C3 = pk2(3.0f, 3.0f);

    __shared__ F2 sx[Ss * 3];       // 12.3 KB, packed (batch b0, b0+1)
    __shared__ F2 part[T * ROWF];   // 6.2 KB

    const int tid = threadIdx.x;
    const int t3  = 3 * tid;
    const int b0  = 2 * blockIdx.x;

    const float* xb = x + (long)b0 * (Ss * 3);
    for (int i = tid; i < Ss * 3; i += TPB)
        sx[i] = pk2(xb[i], xb[i + Ss * 3]);

    // Fold elastic constants into per-point weights:
    //   s0_trial = dot(ws0, x) + ts0 ; s1_trial = dot(ws1, x) + ts1
    //   s3_trial = dot(ws3, x) + ts3 ; pressure = dot(wp, x)
    F2 ws0[3], ws1[3], ws3[3], wp[3], w2p[9];
    {
        const float r0x = W1[tid * 9 + 0], r0y = W1[tid * 9 + 1], r0z = W1[tid * 9 + 2];
        const float r1x = W1[tid * 9 + 3], r1y = W1[tid * 9 + 4], r1z = W1[tid * 9 + 5];
        const float r2x = W1[tid * 9 + 6], r2y = W1[tid * 9 + 7], r2z = W1[tid * 9 + 8];
        const float c23 = TWO_MU * (2.0f / 3.0f);
        const float c13 = TWO_MU * (1.0f / 3.0f);
        const float a0[3] = {c23 * r0x - c13 * r1x, c23 * r0y - c13 * r1y, c23 * r0z - c13 * r1z};
        const float a1[3] = {c23 * r1x - c13 * r0x, c23 * r1y - c13 * r0y, c23 * r1z - c13 * r0z};
        const float a3[3] = {MUv * r2x, MUv * r2y, MUv * r2z};
        const float ap[3] = {Kb * (r0x + r1x), Kb * (r0y + r1y), Kb * (r0z + r1z)};
#pragma unroll
        for (int j = 0; j < 3; ++j) {
            ws0[j] = pk2(a0[j], a0[j]);
            ws1[j] = pk2(a1[j], a1[j]);
            ws3[j] = pk2(a3[j], a3[j]);
            wp[j]  = pk2(ap[j], ap[j]);
        }
    }
#pragma unroll
    for (int o = 0; o < 3; ++o)
#pragma unroll
        for (int j = 0; j < 3; ++j) {
            float w = W2[o * 384 + t3 + j];
            w2p[o * 3 + j] = pk2(w, w);
        }

    // State per half: bex = B*exp(-kappa/C); ivd = 1/(3mu + bex/C).
    // Packed: ts_i = -2mu*ep_i for i in {xx,yy,xy} (zz via tracelessness).
    F2 ts0 = 0, ts1 = 0, ts2 = 0;
    float bexA = Bh, bexB = Bh;
    const float ivd0 = 1.0f / (THREE_MU + Bh * INV_C);
    float ivdA = ivd0, ivdB = ivd0;

    float* ob0 = out + (long)b0 * (Ss * 3);
    float* ob1 = ob0 + Ss * 3;

    __syncthreads();

    for (int s0i = 0; s0i < Ss; s0i += T) {
#pragma unroll
        for (int si = 0; si < T; ++si) {
            const int s = s0i + si;
            const F2 x0 = sx[3 * s + 0];
            const F2 x1 = sx[3 * s + 1];
            const F2 x2 = sx[3 * s + 2];

            // trial deviatoric stress + pressure: folded dot products
            F2 s0d = fma2(ws0[0], x0, fma2(ws0[1], x1, fma2(ws0[2], x2, ts0)));
            F2 s1d = fma2(ws1[0], x0, fma2(ws1[1], x1, fma2(ws1[2], x2, ts1)));
            F2 s3d = fma2(ws3[0], x0, fma2(ws3[1], x1, fma2(ws3[2], x2, ts2)));
            const F2 pr2 = fma2(wp[0], x0, fma2(wp[1], x1, mul2(wp[2], x2)));

            // qsq = 3*(s0^2 + s0*s1 + s1^2 + s3^2)
            F2 acc = mul2(s3d, s3d);
            acc = fma2(s1d, s1d, acc);
            acc = fma2(s0d, s1d, acc);
            acc = fma2(s0d, s0d, acc);
            const F2 qsq2 = mul2(C3, acc);

            float qsA, qsB;
            upk2(qsq2, qsA, qsB);
            qsA = fmaxf(qsA, 1e-24f);
            qsB = fmaxf(qsB, 1e-24f);
            const float rqA = rsqrtf(qsA);
            const float rqB = rsqrtf(qsB);
            const float qaA = qsA * rqA - Ah;   // q - A
            const float qaB = qsB * rqB - Ah;

            // Seed: exact first Newton step from 0, cached slope (no MUFU)
            const float dg0A = fmaxf(qaA + bexA, 0.f) * ivdA;
            const float dg0B = fmaxf(qaB + bexB, 0.f) * ivdB;

            // Newton iteration 1 (exact exp)
            const float BekA = bexA * __expf(dg0A * NINV_C);
            const float BekB = bexB * __expf(dg0B * NINV_C);
            const float rA = fmaf(NEG3MU, dg0A, qaA) + BekA;
            const float rB = fmaf(NEG3MU, dg0B, qaB) + BekB;
            const float dg1A = fmaxf(dg0A + __fdividef(rA, fmaf(BekA, INV_C, THREE_MU)), 0.f);
            const float dg1B = fmaxf(dg0B + __fdividef(rB, fmaf(BekB, INV_C, THREE_MU)), 0.f);

            // Newton iteration 2 (exact exp); reciprocal i2 doubles as the
            // next step's cached seed slope.
            const float Bk2A = bexA * __expf(dg1A * NINV_C);
            const float Bk2B = bexB * __expf(dg1B * NINV_C);
            const float r2A = fmaf(NEG3MU, dg1A, qaA) + Bk2A;
            const float r2B = fmaf(NEG3MU, dg1B, qaB) + Bk2B;
            const float i2A = __fdividef(1.f, fmaf(Bk2A, INV_C, THREE_MU));
            const float i2B = __fdividef(1.f, fmaf(Bk2B, INV_C, THREE_MU));
            const float dg2A = fmaxf(fmaf(r2A, i2A, dg1A), 0.f);
            const float dg2B = fmaxf(fmaf(r2B, i2B, dg1B), 0.f);

            // state refresh: bex at final dg via 1st-order from Bk2
            bexA = Bk2A * fmaf(dg1A - dg2A, INV_C, 1.f);
            bexB = Bk2B * fmaf(dg1B - dg2B, INV_C, 1.f);
            ivdA = i2A;
            ivdB = i2B;

            // radial return: one packed coefficient for stress AND state
            const F2 NN2 = pk2(NEG3MU * dg2A * rqA, NEG3MU * dg2B * rqB);
            ts0 = fma2(NN2, s0d, ts0);
            ts1 = fma2(NN2, s1d, ts1);
            ts2 = fma2(NN2, s3d, ts2);
            s0d = fma2(NN2, s0d, s0d);
            s1d = fma2(NN2, s1d, s1d);
            s3d = fma2(NN2, s3d, s3d);

            const F2 sig0 = add2(s0d, pr2);
            const F2 sig1 = add2(s1d, pr2);

            F2* prp = part + si * ROWF + t3;
            prp[0] = fma2(w2p[0], sig0, fma2(w2p[1], sig1, mul2(w2p[2], s3d)));
            prp[1] = fma2(w2p[3], sig0, fma2(w2p[4], sig1, mul2(w2p[5], s3d)));
            prp[2] = fma2(w2p[6], sig0, fma2(w2p[7], sig1, mul2(w2p[8], s3d)));
        }
        __syncthreads();

        // Reduction: 6 items (si, o) x 16 lanes = 96 threads (3 FULL warps,
        // every slot valid). Each lane sums 8 F2 (stride 16 points), then
        // 4-stage shfl within the 16-lane group; lane0 writes 2 floats.
        if (tid < 96) {
            const int item = tid >> 4;        // 0..5
            const int l16  = tid & 15;
            const int si   = item / 3;
            const int o    = item - 3 * si;
            const F2* prp = part + si * ROWF + o + 3 * l16;
            F2 a0 = 0, a1 = 0, a2 = 0, a3 = 0;
#pragma unroll
            for (int j = 0; j < 8; j += 4) {
                a0 = add2(a0, prp[48 * j]);
                a1 = add2(a1, prp[48 * (j + 1)]);
                a2 = add2(a2, prp[48 * (j + 2)]);
                a3 = add2(a3, prp[48 * (j + 3)]);
            }
            const F2 t = add2(add2(a0, a1), add2(a2, a3));
            float lo, hi;
            upk2(t, lo, hi);
            lo += __shfl_xor_sync(0xffffffffu, lo, 1);
            hi += __shfl_xor_sync(0xffffffffu, hi, 1);
            lo += __shfl_xor_sync(0xffffffffu, lo, 2);
            hi += __shfl_xor_sync(0xffffffffu, hi, 2);
            lo += __shfl_xor_sync(0xffffffffu, lo, 4);
            hi += __shfl_xor_sync(0xffffffffu, hi, 4);
            lo += __shfl_xor_sync(0xffffffffu, lo, 8);
            hi += __shfl_xor_sync(0xffffffffu, hi, 8);
            if (l16 == 0) {
                const int idx = (s0i + si) * 3 + o;
                ob0[idx] = lo;
                ob1[idx] = hi;
            }
        }
        __syncthreads();
    }
}

extern "C" void kernel_launch(void* const* d_in, const int* in_sizes, int n_in,
                              void* d_out, int out_size) {
    const float* x  = (const float*)d_in[0];
    const float* W1 = (const float*)d_in[1];
    const float* W2 = (const float*)d_in[2];
    prnn_kernel<<<Bb / 2, TPB>>>(x, W1, W2, (float*)d_out);
}